// round 16
// baseline (speedup 1.0000x reference)
#include <cuda_runtime.h>
#include <cstdint>

// BorderLoss: mean( w * BCEwithlogits(x, y) ), w = 1 + border(y),
// border = 3x3dilate(y) & ~3x3erode(y), RATIO=2.
// x: [64,512,512] f32, y: [64,512,512] i32 in {0,1}. Output: 1 float.
//
// Identities:
//   loss = softplus((1-2y)*x)        (exact; |x|<~6 so no overflow guard needed)
//   erode = 3x3 AND, dilate = 3x3 OR (binary mask)
//   w=2 on border == +1 to loss exponent (loss >= softplus(-6) ~ 2.5e-3, normal)
//   SAME padding == index clamp (idempotent duplicates under min/max)
//
// Round-16 = Round-15 (fused smem bit-pack + compressed-domain stencil,
// 25.3us @ 68.8% DRAM, 137MB) + software-pipelined x stream: preload row r+1's
// 4x float4 while processing row r. R15 compiled to 32 regs -> only ~1 row of
// x in flight per thread; the explicit double-buffer spends ~16 regs to double
// load-level parallelism at the consumption point (R1 reached 71.8% DRAM at
// 43 regs; R5/R14 showed per-warp batch size directly sets DRAM%).

static constexpr int W  = 512;
static constexpr int H  = 512;
static constexpr int NI = 64;
static constexpr int ROWS_PER_BLOCK = 32;               // 8 warps x 4 rows
static constexpr int GRID = NI * (H / ROWS_PER_BLOCK);  // 1024

__global__ __launch_bounds__(256)
void border_loss_kernel(const float* __restrict__ x,
                        const int*   __restrict__ y,
                        float* __restrict__ out)
{
    const int img      = blockIdx.x >> 4;    // 16 strips of 32 rows per image
    const int strip    = blockIdx.x & 15;
    const int row_base = strip * 32;
    const int warp     = threadIdx.x >> 5;   // 0..7
    const int lane     = threadIdx.x & 31;

    const size_t imgoff = (size_t)img * H * W;

    // ---- Phase A: pack y rows [row_base-1, row_base+32] (clamped) to bits ----
    // sbits[rr][bc] byte = y pixels [bc*8 .. bc*8+7] of global row row_base-1+rr.
    __shared__ unsigned char sbits[34][64];          // 2176 B

    for (int b = threadIdx.x; b < 34 * 64; b += 256) {
        const int rr = b >> 6;          // 0..33
        const int bc = b & 63;
        int gr = row_base - 1 + rr;
        gr = (gr < 0) ? 0 : (gr >= H ? H - 1 : gr);  // SAME-pad clamp
        const int4* p = (const int4*)(y + imgoff + (size_t)gr * W + bc * 8);
        int4 v0 = p[0], v1 = p[1];
        unsigned m0 = __byte_perm(__byte_perm((unsigned)v0.x, (unsigned)v0.y, 0x0040),
                                  __byte_perm((unsigned)v0.z, (unsigned)v0.w, 0x0040),
                                  0x5410) << 7;
        unsigned m1 = __byte_perm(__byte_perm((unsigned)v1.x, (unsigned)v1.y, 0x0040),
                                  __byte_perm((unsigned)v1.z, (unsigned)v1.w, 0x0040),
                                  0x5410) << 7;
        unsigned nib0 = ((m0 & 0x80808080u) * 0x00204081u) >> 28;  // px0 -> bit0
        unsigned nib1 = ((m1 & 0x80808080u) * 0x00204081u) >> 28;
        sbits[rr][bc] = (unsigned char)(nib0 | (nib1 << 4));
    }
    __syncthreads();

    // ---- Phase B: stencil on smem bits + BCE loss on pipelined x stream ----
    const int lr0 = warp * 4;                        // sbits row of top halo
    const float* xbase = x + imgoff + (size_t)(row_base + warp * 4) * W + lane * 16;
    const unsigned short* srow = (const unsigned short*)sbits;  // 32 u16 per row

    unsigned pm = srow[(lr0 + 0) * 32 + lane];
    unsigned cm = srow[(lr0 + 1) * 32 + lane];

    // x double-buffer: row r in xbuf while row r+1 streams into xnext.
    float4 xbuf[4];
    {
        const float4* xr = (const float4*)xbase;
#pragma unroll
        for (int j = 0; j < 4; j++) xbuf[j] = xr[j];
    }

    float acc0 = 0.0f, acc1 = 0.0f;

#pragma unroll
    for (int r = 0; r < 4; r++) {
        float4 xnext[4];
        if (r < 3) {
            const float4* xr = (const float4*)(xbase + (size_t)(r + 1) * W);
#pragma unroll
            for (int j = 0; j < 4; j++) xnext[j] = xr[j];
        }

        unsigned nm = srow[(lr0 + 2 + r) * 32 + lane];

        // Vertical 3-tap on 16-bit rows: AND = erode, OR = dilate
        const unsigned vmn = pm & cm & nm;
        const unsigned vmx = pm | cm | nm;

        // Horizontal halo bits across lanes: pack (mn | mx<<16), 2 shfls.
        const unsigned pk = vmn | (vmx << 16);
        const unsigned eL = __shfl_up_sync(0xffffffffu, pk, 1);
        const unsigned eR = __shfl_down_sync(0xffffffffu, pk, 1);
        unsigned lmn, lmx, rmn, rmx;
        if (lane == 0) { lmn = vmn & 1u;         lmx = vmx & 1u; }          // col clamp
        else           { lmn = (eL >> 15) & 1u;  lmx = eL >> 31; }
        if (lane == 31){ rmn = (vmn >> 15) & 1u; rmx = (vmx >> 15) & 1u; }  // col clamp
        else           { rmn = eR & 1u;          rmx = (eR >> 16) & 1u; }

        const unsigned Lmn = (vmn << 1) | lmn;
        const unsigned Lmx = (vmx << 1) | lmx;
        const unsigned Rmn = (vmn >> 1) | (rmn << 15);
        const unsigned Rmx = (vmx >> 1) | (rmx << 15);

        // border bit k = dilate & ~erode (bits >=16 garbage; masked on use)
        const unsigned border = (vmx | Lmx | Rmx) & ~(vmn & Lmn & Rmn);

        // Loss + weight + accumulate on the buffered row
#pragma unroll
        for (int j = 0; j < 4; j++) {
            float xsv[4] = {xbuf[j].x, xbuf[j].y, xbuf[j].z, xbuf[j].w};
#pragma unroll
            for (int i = 0; i < 4; i++) {
                const int k = j * 4 + i;     // px index 0..15 = bit k
                unsigned s = cm << (31 - k);                 // y bit -> sign bit
                float z = __int_as_float(__float_as_int(xsv[i]) ^ (s & 0x80000000u));
                float l = __logf(1.0f + __expf(z));          // softplus, z in [-6,6]
                unsigned wb = (border << (23 - k)) & 0x00800000u;  // exact *2 on border
                float term = __int_as_float(__float_as_int(l) + wb);
                if (i & 1) acc1 += term; else acc0 += term;  // 2 chains
            }
        }

        // rotate rows + x buffer
        pm = cm; cm = nm;
        if (r < 3) {
#pragma unroll
            for (int j = 0; j < 4; j++) xbuf[j] = xnext[j];
        }
    }

    float acc = acc0 + acc1;

    // ---- block reduce: warp shfl, 8 partials via smem, one REDG per block ----
#pragma unroll
    for (int o = 16; o; o >>= 1)
        acc += __shfl_down_sync(0xffffffffu, acc, o);

    __shared__ float ws[8];
    if (lane == 0) ws[warp] = acc;
    __syncthreads();
    if (threadIdx.x == 0) {
        float s = ((ws[0] + ws[1]) + (ws[2] + ws[3]))
                + ((ws[4] + ws[5]) + (ws[6] + ws[7]));
        atomicAdd(out, s * (1.0f / 16777216.0f));   // return unused -> REDG
    }
}

extern "C" void kernel_launch(void* const* d_in, const int* in_sizes, int n_in,
                              void* d_out, int out_size)
{
    const float* x = (const float*)d_in[0];
    const int*   y = (const int*)d_in[1];
    float* out = (float*)d_out;

    cudaMemsetAsync(out, 0, sizeof(float));          // ~1us node (R9 measured)
    border_loss_kernel<<<GRID, 256>>>(x, y, out);
}

// round 17
// speedup vs baseline: 1.1523x; 1.1523x over previous
#include <cuda_runtime.h>
#include <cstdint>

// BorderLoss: mean( w * BCEwithlogits(x, y) ), w = 1 + border(y),
// border = 3x3dilate(y) & ~3x3erode(y), RATIO=2.
// x: [64,512,512] f32, y: [64,512,512] i32 in {0,1}. Output: 1 float.
//
// Identities:
//   loss = softplus((1-2y)*x)        (exact; |x|<~6 so no overflow guard needed)
//   erode = 3x3 AND, dilate = 3x3 OR (binary mask)
//   w=2 on border == +1 to loss exponent (loss >= softplus(-6) ~ 2.5e-3, normal)
//   SAME padding == index clamp (idempotent duplicates under min/max)
//
// Round-17 = Round-15 (fused smem bit-pack + compressed-domain stencil,
// 25.3us @ 68.8% DRAM — best kernel measured) at FINER BLOCK GRAIN:
// grid 2048, 128-thr blocks, 4 warps x 4 rows. Warp-level code is identical
// (R16 proved per-thread reg-funded MLP kills this family; its MLP comes from
// many light resident warps). R15's grid=1024 was exactly one wave -> kernel
// ends at the slowest SM (spread ~1.2x). 2048 blocks = ~2 balanced waves.
// Cost: y halo 18/16 vs 34/32 = +2MB. Epilogue: memset node + REDG (proven).

static constexpr int W  = 512;
static constexpr int H  = 512;
static constexpr int NI = 64;
static constexpr int ROWS_PER_BLOCK = 16;               // 4 warps x 4 rows
static constexpr int GRID = NI * (H / ROWS_PER_BLOCK);  // 2048

__global__ __launch_bounds__(128)
void border_loss_kernel(const float* __restrict__ x,
                        const int*   __restrict__ y,
                        float* __restrict__ out)
{
    const int img      = blockIdx.x >> 5;    // 32 strips of 16 rows per image
    const int strip    = blockIdx.x & 31;
    const int row_base = strip * 16;
    const int warp     = threadIdx.x >> 5;   // 0..3
    const int lane     = threadIdx.x & 31;

    const size_t imgoff = (size_t)img * H * W;

    // ---- Phase A: pack y rows [row_base-1, row_base+16] (clamped) to bits ----
    // sbits[rr][bc] byte = y pixels [bc*8 .. bc*8+7] of global row row_base-1+rr.
    __shared__ unsigned char sbits[18][64];          // 1152 B

    for (int b = threadIdx.x; b < 18 * 64; b += 128) {
        const int rr = b >> 6;          // 0..17
        const int bc = b & 63;
        int gr = row_base - 1 + rr;
        gr = (gr < 0) ? 0 : (gr >= H ? H - 1 : gr);  // SAME-pad clamp
        const int4* p = (const int4*)(y + imgoff + (size_t)gr * W + bc * 8);
        int4 v0 = p[0], v1 = p[1];
        unsigned m0 = __byte_perm(__byte_perm((unsigned)v0.x, (unsigned)v0.y, 0x0040),
                                  __byte_perm((unsigned)v0.z, (unsigned)v0.w, 0x0040),
                                  0x5410) << 7;
        unsigned m1 = __byte_perm(__byte_perm((unsigned)v1.x, (unsigned)v1.y, 0x0040),
                                  __byte_perm((unsigned)v1.z, (unsigned)v1.w, 0x0040),
                                  0x5410) << 7;
        unsigned nib0 = ((m0 & 0x80808080u) * 0x00204081u) >> 28;  // px0 -> bit0
        unsigned nib1 = ((m1 & 0x80808080u) * 0x00204081u) >> 28;
        sbits[rr][bc] = (unsigned char)(nib0 | (nib1 << 4));
    }
    __syncthreads();

    // ---- Phase B: stencil on smem bits + BCE loss on streamed x ----
    const int lr0 = warp * 4;                        // sbits row of top halo
    const float* xbase = x + imgoff + (size_t)(row_base + warp * 4) * W + lane * 16;
    const unsigned short* srow = (const unsigned short*)sbits;  // 32 u16 per row

    unsigned pm = srow[(lr0 + 0) * 32 + lane];
    unsigned cm = srow[(lr0 + 1) * 32 + lane];

    float acc0 = 0.0f, acc1 = 0.0f;

#pragma unroll
    for (int r = 0; r < 4; r++) {
        unsigned nm = srow[(lr0 + 2 + r) * 32 + lane];

        // Vertical 3-tap on 16-bit rows: AND = erode, OR = dilate
        const unsigned vmn = pm & cm & nm;
        const unsigned vmx = pm | cm | nm;

        // Horizontal halo bits across lanes: pack (mn | mx<<16), 2 shfls.
        const unsigned pk = vmn | (vmx << 16);
        const unsigned eL = __shfl_up_sync(0xffffffffu, pk, 1);
        const unsigned eR = __shfl_down_sync(0xffffffffu, pk, 1);
        unsigned lmn, lmx, rmn, rmx;
        if (lane == 0) { lmn = vmn & 1u;         lmx = vmx & 1u; }          // col clamp
        else           { lmn = (eL >> 15) & 1u;  lmx = eL >> 31; }
        if (lane == 31){ rmn = (vmn >> 15) & 1u; rmx = (vmx >> 15) & 1u; }  // col clamp
        else           { rmn = eR & 1u;          rmx = (eR >> 16) & 1u; }

        const unsigned Lmn = (vmn << 1) | lmn;
        const unsigned Lmx = (vmx << 1) | lmx;
        const unsigned Rmn = (vmn >> 1) | (rmn << 15);
        const unsigned Rmx = (vmx >> 1) | (rmx << 15);

        // border bit k = dilate & ~erode (bits >=16 garbage; masked on use)
        const unsigned border = (vmx | Lmx | Rmx) & ~(vmn & Lmn & Rmn);

        // Loss + weight + accumulate
        const float4* xr = (const float4*)(xbase + (size_t)r * W);
#pragma unroll
        for (int j = 0; j < 4; j++) {
            float4 xv = xr[j];
            float xsv[4] = {xv.x, xv.y, xv.z, xv.w};
#pragma unroll
            for (int i = 0; i < 4; i++) {
                const int k = j * 4 + i;     // px index 0..15 = bit k
                unsigned s = cm << (31 - k);                 // y bit -> sign bit
                float z = __int_as_float(__float_as_int(xsv[i]) ^ (s & 0x80000000u));
                float l = __logf(1.0f + __expf(z));          // softplus, z in [-6,6]
                unsigned wb = (border << (23 - k)) & 0x00800000u;  // exact *2 on border
                float term = __int_as_float(__float_as_int(l) + wb);
                if (i & 1) acc1 += term; else acc0 += term;  // 2 chains
            }
        }

        pm = cm; cm = nm;   // rotate rows
    }

    float acc = acc0 + acc1;

    // ---- block reduce: warp shfl, 4 partials via smem, one REDG per block ----
#pragma unroll
    for (int o = 16; o; o >>= 1)
        acc += __shfl_down_sync(0xffffffffu, acc, o);

    __shared__ float ws[4];
    if (lane == 0) ws[warp] = acc;
    __syncthreads();
    if (threadIdx.x == 0) {
        float s = (ws[0] + ws[1]) + (ws[2] + ws[3]);
        atomicAdd(out, s * (1.0f / 16777216.0f));   // return unused -> REDG
    }
}

extern "C" void kernel_launch(void* const* d_in, const int* in_sizes, int n_in,
                              void* d_out, int out_size)
{
    const float* x = (const float*)d_in[0];
    const int*   y = (const int*)d_in[1];
    float* out = (float*)d_out;

    cudaMemsetAsync(out, 0, sizeof(float));          // ~1us node (R9 measured)
    border_loss_kernel<<<GRID, 128>>>(x, y, out);
}